// round 2
// baseline (speedup 1.0000x reference)
#include <cuda_runtime.h>
#include <cstdint>

#define NN 2048
#define TT 128
#define FF 64
#define HH 128
#define GG 384   // 3*H
#define EE 32768

// ---------------- scratch (device globals: no allocs allowed) ----------------
__device__ float g_deg[NN];
__device__ float g_dinv[NN];
__device__ float g_xs1[NN*HH];
__device__ float g_acc1[NN*HH];
__device__ float g_h1[NN*HH];
__device__ float g_xs2[NN*HH];
__device__ float g_acc2[NN*HH];
__device__ float g_h2[NN*HH];
__device__ float g_wT[HH*GG];     // w_ih transposed: [k][g]
__device__ float g_gi[NN*GG];     // precomputed input gates (+b_ih)
__device__ float g_hist[NN*HH];   // h after each GRU step
__device__ int   g_stride;        // 1 if edge_index is int32, 2 if int64 words

// ---------------- helpers ----------------
__device__ __forceinline__ unsigned long long ffma2(unsigned long long a,
                                                    unsigned long long b,
                                                    unsigned long long c) {
    asm("fma.rn.f32x2 %0, %1, %2, %0;" : "+l"(c) : "l"(a), "l"(b));
    return c;
}
__device__ __forceinline__ float2 unpack2(unsigned long long v) {
    float2 r; asm("mov.b64 {%0,%1}, %2;" : "=f"(r.x), "=f"(r.y) : "l"(v)); return r;
}
__device__ __forceinline__ float fsig(float x) {
    return 1.0f / (1.0f + __expf(-x));
}

// ---------------- kernels ----------------

// Detect int32 vs int64 edge_index by inspecting high words (values < 2048, so
// int64 storage means every odd 32-bit word is zero).
__global__ void k_detect(const int* __restrict__ ei) {
    int any = 0;
    for (int i = threadIdx.x; i < 1024; i += 32) any |= ei[2*i + 1];
    unsigned b = __ballot_sync(0xFFFFFFFFu, any != 0);
    if (threadIdx.x == 0) g_stride = b ? 1 : 2;
}

__global__ void k_init() {
    int i = blockIdx.x * blockDim.x + threadIdx.x;
    if (i < NN*HH) { g_acc1[i] = 0.f; g_acc2[i] = 0.f; }
    if (i < NN)    g_deg[i] = 1.0f;   // self loop
}

__global__ void k_deg(const int* __restrict__ ei) {
    int e = blockIdx.x * blockDim.x + threadIdx.x;
    if (e < EE) {
        int s = g_stride;
        int d = ei[(EE + e) * s];
        atomicAdd(&g_deg[d], 1.0f);
    }
}

__global__ void k_dinv() {
    int n = blockIdx.x * blockDim.x + threadIdx.x;
    if (n < NN) g_dinv[n] = rsqrtf(g_deg[n]);
}

// xs1[n,:] = dinv[n] * (x[n,127,:] @ W1)
__global__ void k_xs1(const float* __restrict__ x, const float* __restrict__ W1) {
    __shared__ float xr[FF];
    int n = blockIdx.x, t = threadIdx.x;
    if (t < FF) xr[t] = x[n*(TT*FF) + 127*FF + t];
    __syncthreads();
    float a = 0.f;
    #pragma unroll
    for (int k = 0; k < FF; k++) a = fmaf(xr[k], W1[k*HH + t], a);
    g_xs1[n*HH + t] = a * g_dinv[n];
}

__global__ void k_scat1(const int* __restrict__ ei) {
    int t = threadIdx.x;
    int e = blockIdx.x * 4 + (t >> 7);
    int j = t & 127;
    int s = g_stride;
    int sr = ei[e * s], d = ei[(EE + e) * s];
    atomicAdd(&g_acc1[d*HH + j], g_xs1[sr*HH + j]);
}

__global__ void k_fin1(const float* __restrict__ b1) {
    int i = blockIdx.x * blockDim.x + threadIdx.x;
    if (i < NN*HH) {
        int n = i >> 7;
        g_h1[i] = g_dinv[n] * (g_acc1[i] + g_xs1[i]) + b1[i & 127];
    }
}

__global__ void k_xs2(const float* __restrict__ W2) {
    __shared__ float hr[HH];
    int n = blockIdx.x, t = threadIdx.x;
    hr[t] = g_h1[n*HH + t];
    __syncthreads();
    float a = 0.f;
    #pragma unroll
    for (int k = 0; k < HH; k++) a = fmaf(hr[k], W2[k*HH + t], a);
    g_xs2[n*HH + t] = a * g_dinv[n];
}

__global__ void k_scat2(const int* __restrict__ ei) {
    int t = threadIdx.x;
    int e = blockIdx.x * 4 + (t >> 7);
    int j = t & 127;
    int s = g_stride;
    int sr = ei[e * s], d = ei[(EE + e) * s];
    atomicAdd(&g_acc2[d*HH + j], g_xs2[sr*HH + j]);
}

__global__ void k_fin2(const float* __restrict__ b2) {
    int i = blockIdx.x * blockDim.x + threadIdx.x;
    if (i < NN*HH) {
        int n = i >> 7;
        g_h2[i] = g_dinv[n] * (g_acc2[i] + g_xs2[i]) + b2[i & 127];
    }
}

__global__ void k_wT(const float* __restrict__ wih) {
    int i = blockIdx.x * blockDim.x + threadIdx.x;
    if (i < GG*HH) { int g = i >> 7, k = i & 127; g_wT[k*GG + g] = wih[i]; }
}

// GI[n,g] = h2[n,:] . w_ih[g,:] + b_ih[g]   (16 rows per block)
__global__ void k_gi(const float* __restrict__ bih) {
    __shared__ float hs[16][HH];
    int g = threadIdx.x;
    int n0 = blockIdx.x * 16;
    for (int i = g; i < 16*HH; i += GG) hs[i >> 7][i & 127] = g_h2[n0*HH + i];
    __syncthreads();
    float acc[16];
    #pragma unroll
    for (int i = 0; i < 16; i++) acc[i] = 0.f;
    for (int k = 0; k < HH; k++) {
        float w = g_wT[k*GG + g];
        #pragma unroll
        for (int i = 0; i < 16; i++) acc[i] = fmaf(hs[i][k], w, acc[i]);
    }
    float b = bih[g];
    #pragma unroll
    for (int i = 0; i < 16; i++) g_gi[(n0 + i)*GG + g] = acc[i] + b;
}

// Sequential GRU over n=0..2047 (the scan axis), hidden = one [128] vector.
// 384 threads: thread tid = gate*128 + j owns the FULL K=128 dot product for
// w_hh row (gate*128 + j). Weights live entirely in registers as 64 x u64
// (f32x2 pairs) = 128 regs/thread; at 384 threads the RF budget is ~170
// regs/thread, so no spills (the previous 512-thread layout spilled).
// h is broadcast from shared (all lanes in a warp read the same address ->
// conflict-free LDS.128). Partial sums exchanged through shared; warps 0-3
// (gate==0) run the gate nonlinearities.
__global__ __launch_bounds__(GG, 1) void k_gru(const float* __restrict__ whh,
                                               const float* __restrict__ bhh) {
    __shared__ __align__(16) float hbuf[2][HH];
    __shared__ float gibuf[2][GG];
    __shared__ float sums[3][HH];

    int tid = threadIdx.x;
    int g = tid >> 7;        // 0=r, 1=z, 2=n
    int j = tid & 127;

    // Load this thread's weight row (128 floats) as 64 packed f32x2 values.
    unsigned long long w[64];
    {
        const ulonglong2* wp = (const ulonglong2*)(whh + (size_t)tid * HH);
        #pragma unroll
        for (int t = 0; t < 32; t++) {
            ulonglong2 v = wp[t];
            w[2*t] = v.x; w[2*t + 1] = v.y;
        }
    }

    float bh_r = 0.f, bh_z = 0.f, bh_n = 0.f, hj = 0.f;
    if (g == 0) { bh_r = bhh[j]; bh_z = bhh[HH + j]; bh_n = bhh[2*HH + j]; }

    if (tid < HH) { hbuf[0][tid] = 0.f; hbuf[1][tid] = 0.f; }
    gibuf[0][tid] = g_gi[tid];
    __syncthreads();

    int p = 0;
    for (int n = 0; n < NN; n++) {
        // prefetch next step's input gates (independent of h -> latency hidden)
        float ginext = 0.f;
        if (n < NN - 1) ginext = g_gi[(size_t)(n + 1)*GG + tid];

        // full dot product: 64 f32x2 FMAs over 4 interleaved accumulators
        const ulonglong2* hp = (const ulonglong2*)(&hbuf[p][0]);
        unsigned long long a0 = 0ull, a1 = 0ull, a2 = 0ull, a3 = 0ull;
        #pragma unroll
        for (int t = 0; t < 32; t += 2) {
            ulonglong2 h0 = hp[t];
            ulonglong2 h1 = hp[t + 1];
            a0 = ffma2(w[2*t],     h0.x, a0);
            a1 = ffma2(w[2*t + 1], h0.y, a1);
            a2 = ffma2(w[2*t + 2], h1.x, a2);
            a3 = ffma2(w[2*t + 3], h1.y, a3);
        }
        float2 f0 = unpack2(a0), f1 = unpack2(a1), f2 = unpack2(a2), f3 = unpack2(a3);
        sums[g][j] = (f0.x + f0.y) + (f1.x + f1.y) + (f2.x + f2.y) + (f3.x + f3.y);
        __syncthreads();

        if (g == 0) {
            float sr = sums[0][j], sz = sums[1][j], sn = sums[2][j];
            float gir = gibuf[p][j], giz = gibuf[p][HH + j], gin = gibuf[p][2*HH + j];
            float r  = fsig(gir + sr + bh_r);
            float z  = fsig(giz + sz + bh_z);
            float ta = gin + r * (sn + bh_n);
            float nn = 2.0f * fsig(2.0f * ta) - 1.0f;     // tanh via sigmoid
            hj = (1.f - z) * nn + z * hj;
            hbuf[p ^ 1][j] = hj;
            g_hist[(size_t)n*HH + j] = hj;
        }
        gibuf[p ^ 1][tid] = ginext;
        __syncthreads();
        p ^= 1;
    }
}

// out[n] = hist[n,:] . fc_w + fc_b  (one warp per n)
__global__ void k_out(const float* __restrict__ fcw, const float* __restrict__ fcb,
                      float* __restrict__ out) {
    int w = threadIdx.x >> 5, lane = threadIdx.x & 31;
    int n = blockIdx.x * 8 + w;
    const float4* hp = (const float4*)(g_hist + (size_t)n*HH);
    const float4* wp = (const float4*)fcw;
    float4 h = hp[lane], ww = wp[lane];
    float s = h.x*ww.x + h.y*ww.y + h.z*ww.z + h.w*ww.w;
    s += __shfl_xor_sync(0xFFFFFFFFu, s, 16);
    s += __shfl_xor_sync(0xFFFFFFFFu, s, 8);
    s += __shfl_xor_sync(0xFFFFFFFFu, s, 4);
    s += __shfl_xor_sync(0xFFFFFFFFu, s, 2);
    s += __shfl_xor_sync(0xFFFFFFFFu, s, 1);
    if (lane == 0) out[n] = s + fcb[0];
}

// ---------------- launch ----------------
extern "C" void kernel_launch(void* const* d_in, const int* in_sizes, int n_in,
                              void* d_out, int out_size) {
    const float* x   = (const float*)d_in[0];
    const int*   ei  = (const int*)  d_in[1];
    const float* W1  = (const float*)d_in[2];
    const float* b1  = (const float*)d_in[3];
    const float* W2  = (const float*)d_in[4];
    const float* b2  = (const float*)d_in[5];
    const float* wih = (const float*)d_in[6];
    const float* whh = (const float*)d_in[7];
    const float* bih = (const float*)d_in[8];
    const float* bhh = (const float*)d_in[9];
    const float* fcw = (const float*)d_in[10];
    const float* fcb = (const float*)d_in[11];
    float* out = (float*)d_out;

    k_detect<<<1, 32>>>(ei);
    k_init<<<(NN*HH + 255)/256, 256>>>();
    k_deg<<<EE/256, 256>>>(ei);
    k_dinv<<<(NN + 255)/256, 256>>>();
    k_xs1<<<NN, HH>>>(x, W1);
    k_scat1<<<EE/4, 512>>>(ei);
    k_fin1<<<NN*HH/256, 256>>>(b1);
    k_xs2<<<NN, HH>>>(W2);
    k_scat2<<<EE/4, 512>>>(ei);
    k_fin2<<<NN*HH/256, 256>>>(b2);
    k_wT<<<GG*HH/256, 256>>>(wih);
    k_gi<<<NN/16, GG>>>(bih);
    k_gru<<<1, GG>>>(whh, bhh);
    k_out<<<NN/8, 256>>>(fcw, fcb, out);
}